// round 1
// baseline (speedup 1.0000x reference)
#include <cuda_runtime.h>

#define DM 1024
#define NH 16
#define HD 64
#define SQ 2048
#define BB 4
#define MT (BB*SQ)   // 8192 rows total

// Scratch (no allocations allowed -> __device__ globals). 4 x 32 MB.
__device__ float g_Q[(size_t)MT * DM];
__device__ float g_K[(size_t)MT * DM];
__device__ float g_V[(size_t)MT * DM];
__device__ float g_C[(size_t)MT * DM];

// ---------------------------------------------------------------------------
// 128x128x16 register-blocked SGEMM: C[M,N] = A[M,K] @ W[N,K]^T (+bias)
// 256 threads, 8x8 per-thread microtile. M,N multiples of 128; K of 16.
// ---------------------------------------------------------------------------
__device__ __forceinline__ void gemm128(const float* __restrict__ A,
                                        const float* __restrict__ W,
                                        const float* __restrict__ bias,
                                        float* __restrict__ C)
{
    __shared__ float Ast[16][128];
    __shared__ float Wst[16][128];
    const int tid = threadIdx.x;
    const int ty = tid >> 4, tx = tid & 15;
    const int m0 = blockIdx.y * 128;
    const int n0 = blockIdx.x * 128;
    const int lr = tid >> 1;          // 0..127 row within tile
    const int hb = (tid & 1) * 8;     // which half of the 16 k-columns

    float acc[8][8];
#pragma unroll
    for (int i = 0; i < 8; i++)
#pragma unroll
        for (int j = 0; j < 8; j++) acc[i][j] = 0.f;

    for (int k0 = 0; k0 < DM; k0 += 16) {
#pragma unroll
        for (int rep = 0; rep < 2; rep++) {
            const int col = hb + rep * 4;
            float4 av = *(const float4*)&A[(size_t)(m0 + lr) * DM + k0 + col];
            Ast[col + 0][lr] = av.x; Ast[col + 1][lr] = av.y;
            Ast[col + 2][lr] = av.z; Ast[col + 3][lr] = av.w;
            float4 wv = *(const float4*)&W[(size_t)(n0 + lr) * DM + k0 + col];
            Wst[col + 0][lr] = wv.x; Wst[col + 1][lr] = wv.y;
            Wst[col + 2][lr] = wv.z; Wst[col + 3][lr] = wv.w;
        }
        __syncthreads();
#pragma unroll
        for (int kk = 0; kk < 16; kk++) {
            float4 a0 = *(const float4*)&Ast[kk][ty * 8];
            float4 a1 = *(const float4*)&Ast[kk][ty * 8 + 4];
            float4 b0 = *(const float4*)&Wst[kk][tx * 8];
            float4 b1 = *(const float4*)&Wst[kk][tx * 8 + 4];
            float a[8] = {a0.x, a0.y, a0.z, a0.w, a1.x, a1.y, a1.z, a1.w};
            float b[8] = {b0.x, b0.y, b0.z, b0.w, b1.x, b1.y, b1.z, b1.w};
#pragma unroll
            for (int i = 0; i < 8; i++)
#pragma unroll
                for (int j = 0; j < 8; j++)
                    acc[i][j] = fmaf(a[i], b[j], acc[i][j]);
        }
        __syncthreads();
    }

    float bj[8];
#pragma unroll
    for (int j = 0; j < 8; j++) bj[j] = bias ? bias[n0 + tx * 8 + j] : 0.f;
#pragma unroll
    for (int i = 0; i < 8; i++) {
        float* dst = &C[(size_t)(m0 + ty * 8 + i) * DM + n0 + tx * 8];
        float4 o0 = make_float4(acc[i][0] + bj[0], acc[i][1] + bj[1],
                                acc[i][2] + bj[2], acc[i][3] + bj[3]);
        float4 o1 = make_float4(acc[i][4] + bj[4], acc[i][5] + bj[5],
                                acc[i][6] + bj[6], acc[i][7] + bj[7]);
        *(float4*)dst = o0;
        *(float4*)(dst + 4) = o1;
    }
}

__global__ __launch_bounds__(256) void qkv_gemm_kernel(
    const float* __restrict__ x,
    const float* __restrict__ Wq,
    const float* __restrict__ Wk,
    const float* __restrict__ Wv)
{
    const float* W;
    float* C;
    if (blockIdx.z == 0)      { W = Wq; C = g_Q; }
    else if (blockIdx.z == 1) { W = Wk; C = g_K; }
    else                      { W = Wv; C = g_V; }
    gemm128(x, W, nullptr, C);
}

__global__ __launch_bounds__(256) void o_gemm_kernel(
    const float* __restrict__ Wo,
    const float* __restrict__ bo,
    float* __restrict__ out)
{
    gemm128(g_C, Wo, bo, out);
}

// ---------------------------------------------------------------------------
// Flash attention with relative position bias.
// Grid: (S/64, B*H). 256 threads (16x16), 4x4 microtiles over 64x64 tiles.
// ---------------------------------------------------------------------------
#define ATTN_SMEM_FLOATS (4 * 4096 + 128)
#define ATTN_SMEM_BYTES  (ATTN_SMEM_FLOATS * 4)

__device__ __forceinline__ float redmax16(float v)
{
#pragma unroll
    for (int o = 8; o; o >>= 1) v = fmaxf(v, __shfl_xor_sync(0xffffffffu, v, o));
    return v;
}
__device__ __forceinline__ float redsum16(float v)
{
#pragma unroll
    for (int o = 8; o; o >>= 1) v += __shfl_xor_sync(0xffffffffu, v, o);
    return v;
}

__global__ __launch_bounds__(256) void attn_kernel(const float* __restrict__ bt)
{
    extern __shared__ float sm[];
    float* Qs  = sm;              // [64][64] row-major (q-row, d)
    float* Kst = sm + 4096;       // [64][64] (d, k-col)  -- transposed
    float* Vs  = sm + 8192;       // [64][64] (k-row, e)
    float* Ps  = sm + 12288;      // [64][64] (q-row, k-col)
    float* bs  = sm + 16384;      // [127] bias diagonal window

    const int tid = threadIdx.x;
    const int ty = tid >> 4, tx = tid & 15;
    const int bh = blockIdx.y;
    const int b = bh >> 4, h = bh & 15;
    const int q0 = blockIdx.x * 64;

    // Load Q tile (once)
    {
        const int r = tid >> 2;
        const int f = (tid & 3) * 4;
        const float* src = g_Q + (size_t)(b * SQ + q0 + r) * DM + h * HD;
#pragma unroll
        for (int rep = 0; rep < 4; rep++) {
            const int d = f + rep * 16;
            *(float4*)&Qs[r * 64 + d] = *(const float4*)&src[d];
        }
    }

    float m_i[4], l_i[4], acc[4][4];
#pragma unroll
    for (int i = 0; i < 4; i++) {
        m_i[i] = -1e30f; l_i[i] = 0.f;
#pragma unroll
        for (int j = 0; j < 4; j++) acc[i][j] = 0.f;
    }

    for (int k0 = 0; k0 < SQ; k0 += 64) {
        __syncthreads();   // protect Kst/Vs/Ps from previous iteration's readers
        {
            const int r = tid >> 2;
            const int f = (tid & 3) * 4;
            const float* ks = g_K + (size_t)(b * SQ + k0 + r) * DM + h * HD;
            const float* vs = g_V + (size_t)(b * SQ + k0 + r) * DM + h * HD;
#pragma unroll
            for (int rep = 0; rep < 4; rep++) {
                const int d = f + rep * 16;
                float4 kv = *(const float4*)&ks[d];
                Kst[(d + 0) * 64 + r] = kv.x;
                Kst[(d + 1) * 64 + r] = kv.y;
                Kst[(d + 2) * 64 + r] = kv.z;
                Kst[(d + 3) * 64 + r] = kv.w;
                *(float4*)&Vs[r * 64 + d] = *(const float4*)&vs[d];
            }
            // bias window: diff = q-k in [q0-k0-63, q0-k0+63]; idx = diff+2047
            const int base = q0 - k0 + 1984;
            if (tid < 127) bs[tid] = bt[(base + tid) * NH + h];
        }
        __syncthreads();

        // S = Q @ K^T
        float s[4][4];
#pragma unroll
        for (int i = 0; i < 4; i++)
#pragma unroll
            for (int j = 0; j < 4; j++) s[i][j] = 0.f;

#pragma unroll
        for (int d = 0; d < 64; d += 4) {
            float4 k0v = *(const float4*)&Kst[(d + 0) * 64 + tx * 4];
            float4 k1v = *(const float4*)&Kst[(d + 1) * 64 + tx * 4];
            float4 k2v = *(const float4*)&Kst[(d + 2) * 64 + tx * 4];
            float4 k3v = *(const float4*)&Kst[(d + 3) * 64 + tx * 4];
#pragma unroll
            for (int i = 0; i < 4; i++) {
                float4 qa = *(const float4*)&Qs[(ty * 4 + i) * 64 + d];
                s[i][0] = fmaf(qa.x, k0v.x, fmaf(qa.y, k1v.x, fmaf(qa.z, k2v.x, fmaf(qa.w, k3v.x, s[i][0]))));
                s[i][1] = fmaf(qa.x, k0v.y, fmaf(qa.y, k1v.y, fmaf(qa.z, k2v.y, fmaf(qa.w, k3v.y, s[i][1]))));
                s[i][2] = fmaf(qa.x, k0v.z, fmaf(qa.y, k1v.z, fmaf(qa.z, k2v.z, fmaf(qa.w, k3v.z, s[i][2]))));
                s[i][3] = fmaf(qa.x, k0v.w, fmaf(qa.y, k1v.w, fmaf(qa.z, k2v.w, fmaf(qa.w, k3v.w, s[i][3]))));
            }
        }

        // scale + relative bias + online softmax
#pragma unroll
        for (int i = 0; i < 4; i++) {
            const int r = ty * 4 + i;
#pragma unroll
            for (int j = 0; j < 4; j++)
                s[i][j] = s[i][j] * 0.125f + bs[r - (tx * 4 + j) + 63];
            float rmax = fmaxf(fmaxf(s[i][0], s[i][1]), fmaxf(s[i][2], s[i][3]));
            rmax = redmax16(rmax);
            const float mnew = fmaxf(m_i[i], rmax);
            const float corr = __expf(m_i[i] - mnew);
            float rsum = 0.f;
#pragma unroll
            for (int j = 0; j < 4; j++) { s[i][j] = __expf(s[i][j] - mnew); rsum += s[i][j]; }
            rsum = redsum16(rsum);
            l_i[i] = l_i[i] * corr + rsum;
            m_i[i] = mnew;
#pragma unroll
            for (int j = 0; j < 4; j++) acc[i][j] *= corr;
            *(float4*)&Ps[r * 64 + tx * 4] = make_float4(s[i][0], s[i][1], s[i][2], s[i][3]);
        }
        __syncthreads();

        // acc += P @ V
#pragma unroll
        for (int kk = 0; kk < 64; kk += 4) {
            float4 v0 = *(const float4*)&Vs[(kk + 0) * 64 + tx * 4];
            float4 v1 = *(const float4*)&Vs[(kk + 1) * 64 + tx * 4];
            float4 v2 = *(const float4*)&Vs[(kk + 2) * 64 + tx * 4];
            float4 v3 = *(const float4*)&Vs[(kk + 3) * 64 + tx * 4];
#pragma unroll
            for (int i = 0; i < 4; i++) {
                float4 pa = *(const float4*)&Ps[(ty * 4 + i) * 64 + kk];
                acc[i][0] = fmaf(pa.x, v0.x, fmaf(pa.y, v1.x, fmaf(pa.z, v2.x, fmaf(pa.w, v3.x, acc[i][0]))));
                acc[i][1] = fmaf(pa.x, v0.y, fmaf(pa.y, v1.y, fmaf(pa.z, v2.y, fmaf(pa.w, v3.y, acc[i][1]))));
                acc[i][2] = fmaf(pa.x, v0.z, fmaf(pa.y, v1.z, fmaf(pa.z, v2.z, fmaf(pa.w, v3.z, acc[i][2]))));
                acc[i][3] = fmaf(pa.x, v0.w, fmaf(pa.y, v1.w, fmaf(pa.z, v2.w, fmaf(pa.w, v3.w, acc[i][3]))));
            }
        }
    }

    // normalize and write ctx in [B,S,D] layout
#pragma unroll
    for (int i = 0; i < 4; i++) {
        const float inv = 1.f / l_i[i];
        float4 o = make_float4(acc[i][0] * inv, acc[i][1] * inv,
                               acc[i][2] * inv, acc[i][3] * inv);
        *(float4*)&g_C[(size_t)(b * SQ + q0 + ty * 4 + i) * DM + h * HD + tx * 4] = o;
    }
}

// ---------------------------------------------------------------------------
extern "C" void kernel_launch(void* const* d_in, const int* in_sizes, int n_in,
                              void* d_out, int out_size)
{
    (void)in_sizes; (void)n_in; (void)out_size;
    const float* x   = (const float*)d_in[0];
    const float* Wq  = (const float*)d_in[1];
    const float* Wk  = (const float*)d_in[2];
    const float* Wv  = (const float*)d_in[3];
    const float* Wo  = (const float*)d_in[4];
    const float* bo  = (const float*)d_in[5];
    const float* bt  = (const float*)d_in[6];
    float* out = (float*)d_out;

    // 1) QKV projections (fused over blockIdx.z)
    dim3 g1(DM / 128, MT / 128, 3);
    qkv_gemm_kernel<<<g1, 256>>>(x, Wq, Wk, Wv);

    // 2) attention
    cudaFuncSetAttribute(attn_kernel,
                         cudaFuncAttributeMaxDynamicSharedMemorySize,
                         ATTN_SMEM_BYTES);
    dim3 g2(SQ / 64, BB * NH);
    attn_kernel<<<g2, 256, ATTN_SMEM_BYTES>>>(bt);

    // 3) output projection + bias
    dim3 g3(DM / 128, MT / 128);
    o_gemm_kernel<<<g3, 256>>>(Wo, bo, out);
}

// round 3
// speedup vs baseline: 3.3924x; 3.3924x over previous
#include <cuda_runtime.h>

#define DM 1024
#define NH 16
#define HD 64
#define SQ 2048
#define BB 4
#define MT (BB*SQ)   // 8192 rows total

// Scratch (no allocations allowed -> __device__ globals). 4 x 32 MB.
__device__ float g_Q[(size_t)MT * DM];
__device__ float g_K[(size_t)MT * DM];
__device__ float g_V[(size_t)MT * DM];
__device__ float g_C[(size_t)MT * DM];

// ---------------------------------------------------------------------------
// helpers
// ---------------------------------------------------------------------------
__device__ __forceinline__ unsigned f2tf(float f)
{
    unsigned u;
    asm("cvt.rna.tf32.f32 %0, %1;" : "=r"(u) : "f"(f));
    return u;
}
__device__ __forceinline__ float tfbits(float f)   // fp32 value rounded to tf32
{
    return __uint_as_float(f2tf(f));
}
__device__ __forceinline__ void mma_tf32(float c[4], const unsigned a[4],
                                         const unsigned b[2])
{
    asm volatile(
        "mma.sync.aligned.m16n8k8.row.col.f32.tf32.tf32.f32 "
        "{%0,%1,%2,%3},{%4,%5,%6,%7},{%8,%9},{%0,%1,%2,%3};"
        : "+f"(c[0]), "+f"(c[1]), "+f"(c[2]), "+f"(c[3])
        : "r"(a[0]), "r"(a[1]), "r"(a[2]), "r"(a[3]), "r"(b[0]), "r"(b[1]));
}

// ---------------------------------------------------------------------------
// TF32 tensor-core SGEMM: C[M,N] = A[M,K] @ W[N,K]^T (+bias)
// Block 128x128, K-chunk 32, 8 warps -> warp tile 64x32 (warp grid 2x4).
// smem rows padded to 36 floats: fragment LDS bank = lane -> conflict-free.
// ---------------------------------------------------------------------------
#define KT 32
#define PAD 36

__device__ __forceinline__ void gemm128_tc(const float* __restrict__ A,
                                           const float* __restrict__ W,
                                           const float* __restrict__ bias,
                                           float* __restrict__ C)
{
    __shared__ float As[128][PAD];
    __shared__ float Bs[128][PAD];

    const int tid  = threadIdx.x;
    const int warp = tid >> 5, lane = tid & 31;
    const int wm = warp >> 2, wn = warp & 3;
    const int lg = lane >> 2, lt = lane & 3;   // groupID, threadID_in_group
    const int m0 = blockIdx.y * 128;
    const int n0 = blockIdx.x * 128;

    float acc[4][4][4];
#pragma unroll
    for (int i = 0; i < 4; i++)
#pragma unroll
        for (int j = 0; j < 4; j++)
#pragma unroll
            for (int e = 0; e < 4; e++) acc[i][j][e] = 0.f;

    const int lr = tid >> 3;            // 0..31
    const int lc = (tid & 7) * 4;       // float4 col within 32-wide K chunk

    for (int k0 = 0; k0 < DM; k0 += KT) {
#pragma unroll
        for (int rep = 0; rep < 4; rep++) {
            const int row = lr + rep * 32;
            float4 av = *(const float4*)&A[(size_t)(m0 + row) * DM + k0 + lc];
            float4 wv = *(const float4*)&W[(size_t)(n0 + row) * DM + k0 + lc];
            av.x = tfbits(av.x); av.y = tfbits(av.y);
            av.z = tfbits(av.z); av.w = tfbits(av.w);
            wv.x = tfbits(wv.x); wv.y = tfbits(wv.y);
            wv.z = tfbits(wv.z); wv.w = tfbits(wv.w);
            *(float4*)&As[row][lc] = av;
            *(float4*)&Bs[row][lc] = wv;
        }
        __syncthreads();

#pragma unroll
        for (int ks = 0; ks < 4; ks++) {
            unsigned a[4][4], b[4][2];
#pragma unroll
            for (int mt = 0; mt < 4; mt++) {
                const int r = wm * 64 + mt * 16 + lg;
                const int c = ks * 8 + lt;
                a[mt][0] = __float_as_uint(As[r][c]);
                a[mt][1] = __float_as_uint(As[r + 8][c]);
                a[mt][2] = __float_as_uint(As[r][c + 4]);
                a[mt][3] = __float_as_uint(As[r + 8][c + 4]);
            }
#pragma unroll
            for (int nt = 0; nt < 4; nt++) {
                const int r = wn * 32 + nt * 8 + lg;
                const int c = ks * 8 + lt;
                b[nt][0] = __float_as_uint(Bs[r][c]);
                b[nt][1] = __float_as_uint(Bs[r][c + 4]);
            }
#pragma unroll
            for (int mt = 0; mt < 4; mt++)
#pragma unroll
                for (int nt = 0; nt < 4; nt++)
                    mma_tf32(acc[mt][nt], a[mt], b[nt]);
        }
        __syncthreads();
    }

    // epilogue
#pragma unroll
    for (int mt = 0; mt < 4; mt++) {
        const int r0 = m0 + wm * 64 + mt * 16 + lg;
#pragma unroll
        for (int nt = 0; nt < 4; nt++) {
            const int col = n0 + wn * 32 + nt * 8 + 2 * lt;
            float b0 = 0.f, b1 = 0.f;
            if (bias) { b0 = bias[col]; b1 = bias[col + 1]; }
            *(float2*)&C[(size_t)r0 * DM + col] =
                make_float2(acc[mt][nt][0] + b0, acc[mt][nt][1] + b1);
            *(float2*)&C[(size_t)(r0 + 8) * DM + col] =
                make_float2(acc[mt][nt][2] + b0, acc[mt][nt][3] + b1);
        }
    }
}

__global__ __launch_bounds__(256, 2) void qkv_gemm_kernel(
    const float* __restrict__ x,
    const float* __restrict__ Wq,
    const float* __restrict__ Wk,
    const float* __restrict__ Wv)
{
    const float* W;
    float* C;
    if (blockIdx.z == 0)      { W = Wq; C = g_Q; }
    else if (blockIdx.z == 1) { W = Wk; C = g_K; }
    else                      { W = Wv; C = g_V; }
    gemm128_tc(x, W, nullptr, C);
}

__global__ __launch_bounds__(256, 2) void o_gemm_kernel(
    const float* __restrict__ Wo,
    const float* __restrict__ bo,
    float* __restrict__ out)
{
    gemm128_tc(g_C, Wo, bo, out);
}

// ---------------------------------------------------------------------------
// Flash attention, TF32 tensor cores.
// Block: 128 queries x full key loop (64-key tiles). 256 threads, 8 warps;
// each warp owns 16 full query rows -> softmax reductions are 4-lane shfls.
// ---------------------------------------------------------------------------
#define APAD 68
#define KS_OFF   0
#define VST_OFF  (64 * APAD)            // 4352
#define PS_OFF   (2 * 64 * APAD)        // 8704
#define BS_OFF   (PS_OFF + 128 * APAD)  // 17408
#define ATTN_SMEM_FLOATS (BS_OFF + 192)
#define ATTN_SMEM_BYTES  (ATTN_SMEM_FLOATS * 4)

__global__ __launch_bounds__(256, 2) void attn_kernel(const float* __restrict__ bt)
{
    extern __shared__ float sm[];
    float* Ks  = sm + KS_OFF;    // [64][APAD]  (kcol, d)  = B col-major for QK^T
    float* Vst = sm + VST_OFF;   // [64][APAD]  (d, kk)    = B col-major for P@V
    float* Ps  = sm + PS_OFF;    // [128][APAD] per-warp P rows (Q staging at init)
    float* bs  = sm + BS_OFF;    // [192] bias diagonal window

    const int tid  = threadIdx.x;
    const int warp = tid >> 5, lane = tid & 31;
    const int lg = lane >> 2, lt = lane & 3;
    const int bh = blockIdx.y;
    const int b = bh >> 4, h = bh & 15;
    const int q0 = blockIdx.x * 128;

    // ---- stage Q (scaled by 1/8, tf32) into Ps, pull fragments to registers
    {
        const int r = tid >> 1;
        const int c0 = (tid & 1) * 32;
        const float* src = g_Q + (size_t)(b * SQ + q0 + r) * DM + h * HD;
#pragma unroll
        for (int rep = 0; rep < 8; rep++) {
            float4 v = *(const float4*)&src[c0 + rep * 4];
            v.x = tfbits(v.x * 0.125f); v.y = tfbits(v.y * 0.125f);
            v.z = tfbits(v.z * 0.125f); v.w = tfbits(v.w * 0.125f);
            *(float4*)&Ps[r * APAD + c0 + rep * 4] = v;
        }
    }
    __syncthreads();

    unsigned qf[8][4];
    {
        const int r = warp * 16 + lg;
#pragma unroll
        for (int ks = 0; ks < 8; ks++) {
            const int c = ks * 8 + lt;
            qf[ks][0] = __float_as_uint(Ps[r * APAD + c]);
            qf[ks][1] = __float_as_uint(Ps[(r + 8) * APAD + c]);
            qf[ks][2] = __float_as_uint(Ps[r * APAD + c + 4]);
            qf[ks][3] = __float_as_uint(Ps[(r + 8) * APAD + c + 4]);
        }
    }
    __syncthreads();

    const int r0 = warp * 16 + lg;     // tile-local query rows of this thread
    const int r1 = r0 + 8;

    float m0v = -1e30f, m1v = -1e30f, l0v = 0.f, l1v = 0.f;
    float o[8][4];
#pragma unroll
    for (int nt = 0; nt < 8; nt++)
#pragma unroll
        for (int e = 0; e < 4; e++) o[nt][e] = 0.f;

    for (int k0 = 0; k0 < SQ; k0 += 64) {
        __syncthreads();   // previous iteration's K/V readers done
        {
            const int r = tid >> 2;
            const float* ksrc = g_K + (size_t)(b * SQ + k0 + r) * DM + h * HD;
            const float* vsrc = g_V + (size_t)(b * SQ + k0 + r) * DM + h * HD;
#pragma unroll
            for (int rep = 0; rep < 4; rep++) {
                const int d = (tid & 3) * 4 + rep * 16;
                float4 kv = *(const float4*)&ksrc[d];
                kv.x = tfbits(kv.x); kv.y = tfbits(kv.y);
                kv.z = tfbits(kv.z); kv.w = tfbits(kv.w);
                *(float4*)&Ks[r * APAD + d] = kv;
                float4 vv = *(const float4*)&vsrc[d];
                Vst[(d + 0) * APAD + r] = tfbits(vv.x);
                Vst[(d + 1) * APAD + r] = tfbits(vv.y);
                Vst[(d + 2) * APAD + r] = tfbits(vv.z);
                Vst[(d + 3) * APAD + r] = tfbits(vv.w);
            }
            if (tid < 191) bs[tid] = bt[(q0 - k0 + 1984 + tid) * NH + h];
        }
        __syncthreads();

        // ---- S = (Q/8) @ K^T
        float s[8][4];
#pragma unroll
        for (int nt = 0; nt < 8; nt++)
#pragma unroll
            for (int e = 0; e < 4; e++) s[nt][e] = 0.f;

#pragma unroll
        for (int ks = 0; ks < 8; ks++) {
#pragma unroll
            for (int nt = 0; nt < 8; nt++) {
                unsigned bf[2];
                const int n = nt * 8 + lg;
                const int c = ks * 8 + lt;
                bf[0] = __float_as_uint(Ks[n * APAD + c]);
                bf[1] = __float_as_uint(Ks[n * APAD + c + 4]);
                mma_tf32(s[nt], qf[ks], bf);
            }
        }

        // ---- bias + online softmax (rows r0, r1 fully within this warp)
        float mx0 = -1e30f, mx1 = -1e30f;
#pragma unroll
        for (int nt = 0; nt < 8; nt++) {
            const int col = nt * 8 + 2 * lt;
            s[nt][0] += bs[r0 - col + 63];
            s[nt][1] += bs[r0 - col + 62];
            s[nt][2] += bs[r1 - col + 63];
            s[nt][3] += bs[r1 - col + 62];
            mx0 = fmaxf(mx0, fmaxf(s[nt][0], s[nt][1]));
            mx1 = fmaxf(mx1, fmaxf(s[nt][2], s[nt][3]));
        }
#pragma unroll
        for (int off = 1; off <= 2; off <<= 1) {
            mx0 = fmaxf(mx0, __shfl_xor_sync(0xffffffffu, mx0, off));
            mx1 = fmaxf(mx1, __shfl_xor_sync(0xffffffffu, mx1, off));
        }
        const float mn0 = fmaxf(m0v, mx0);
        const float mn1 = fmaxf(m1v, mx1);
        const float cr0 = __expf(m0v - mn0);
        const float cr1 = __expf(m1v - mn1);
        float sum0 = 0.f, sum1 = 0.f;
#pragma unroll
        for (int nt = 0; nt < 8; nt++) {
            s[nt][0] = __expf(s[nt][0] - mn0);
            s[nt][1] = __expf(s[nt][1] - mn0);
            s[nt][2] = __expf(s[nt][2] - mn1);
            s[nt][3] = __expf(s[nt][3] - mn1);
            sum0 += s[nt][0] + s[nt][1];
            sum1 += s[nt][2] + s[nt][3];
            const int col = nt * 8 + 2 * lt;
            *(float2*)&Ps[r0 * APAD + col] =
                make_float2(tfbits(s[nt][0]), tfbits(s[nt][1]));
            *(float2*)&Ps[r1 * APAD + col] =
                make_float2(tfbits(s[nt][2]), tfbits(s[nt][3]));
        }
#pragma unroll
        for (int off = 1; off <= 2; off <<= 1) {
            sum0 += __shfl_xor_sync(0xffffffffu, sum0, off);
            sum1 += __shfl_xor_sync(0xffffffffu, sum1, off);
        }
        l0v = l0v * cr0 + sum0;
        l1v = l1v * cr1 + sum1;
        m0v = mn0; m1v = mn1;
#pragma unroll
        for (int nt = 0; nt < 8; nt++) {
            o[nt][0] *= cr0; o[nt][1] *= cr0;
            o[nt][2] *= cr1; o[nt][3] *= cr1;
        }
        __syncwarp();   // P rows visible within warp

        // ---- acc += P @ V
#pragma unroll
        for (int ks = 0; ks < 8; ks++) {
            unsigned pa[4];
            const int c = ks * 8 + lt;
            pa[0] = __float_as_uint(Ps[r0 * APAD + c]);
            pa[1] = __float_as_uint(Ps[r1 * APAD + c]);
            pa[2] = __float_as_uint(Ps[r0 * APAD + c + 4]);
            pa[3] = __float_as_uint(Ps[r1 * APAD + c + 4]);
#pragma unroll
            for (int nt = 0; nt < 8; nt++) {
                unsigned bf[2];
                const int n = nt * 8 + lg;
                bf[0] = __float_as_uint(Vst[n * APAD + c]);
                bf[1] = __float_as_uint(Vst[n * APAD + c + 4]);
                mma_tf32(o[nt], pa, bf);
            }
        }
    }

    // ---- normalize + write ctx [B,S,D]
    const float inv0 = 1.f / l0v;
    const float inv1 = 1.f / l1v;
    float* dst0 = g_C + (size_t)(b * SQ + q0 + r0) * DM + h * HD;
    float* dst1 = g_C + (size_t)(b * SQ + q0 + r1) * DM + h * HD;
#pragma unroll
    for (int nt = 0; nt < 8; nt++) {
        const int col = nt * 8 + 2 * lt;
        *(float2*)&dst0[col] = make_float2(o[nt][0] * inv0, o[nt][1] * inv0);
        *(float2*)&dst1[col] = make_float2(o[nt][2] * inv1, o[nt][3] * inv1);
    }
}

// ---------------------------------------------------------------------------
extern "C" void kernel_launch(void* const* d_in, const int* in_sizes, int n_in,
                              void* d_out, int out_size)
{
    (void)in_sizes; (void)n_in; (void)out_size;
    const float* x   = (const float*)d_in[0];
    const float* Wq  = (const float*)d_in[1];
    const float* Wk  = (const float*)d_in[2];
    const float* Wv  = (const float*)d_in[3];
    const float* Wo  = (const float*)d_in[4];
    const float* bo  = (const float*)d_in[5];
    const float* bt  = (const float*)d_in[6];
    float* out = (float*)d_out;

    dim3 g1(DM / 128, MT / 128, 3);
    qkv_gemm_kernel<<<g1, 256>>>(x, Wq, Wk, Wv);

    cudaFuncSetAttribute(attn_kernel,
                         cudaFuncAttributeMaxDynamicSharedMemorySize,
                         ATTN_SMEM_BYTES);
    dim3 g2(SQ / 128, BB * NH);
    attn_kernel<<<g2, 256, ATTN_SMEM_BYTES>>>(bt);

    dim3 g3(DM / 128, MT / 128);
    o_gemm_kernel<<<g3, 256>>>(Wo, bo, out);
}

// round 5
// speedup vs baseline: 3.6267x; 1.0691x over previous
#include <cuda_runtime.h>

#define DM 1024
#define NH 16
#define HD 64
#define SQ 2048
#define BB 4
#define MT (BB*SQ)   // 8192 rows total

// Scratch (no allocations allowed -> __device__ globals).
__device__ float g_X [(size_t)MT * DM];          // x, tf32
__device__ float g_Wt[(size_t)4 * DM * DM];      // Wq/8, Wk, Wv, Wo  (tf32)
__device__ float g_Q [(size_t)MT * DM];          // q/8, tf32
__device__ float g_K [(size_t)MT * DM];          // k, tf32
__device__ float g_Vt[(size_t)MT * DM];          // v^T per (b,h): [64][SQ], tf32
__device__ float g_C [(size_t)MT * DM];          // ctx, tf32

// ---------------------------------------------------------------------------
// helpers
// ---------------------------------------------------------------------------
__device__ __forceinline__ float tfbits(float f)
{
    unsigned u;
    asm("cvt.rna.tf32.f32 %0, %1;" : "=r"(u) : "f"(f));
    return __uint_as_float(u);
}
__device__ __forceinline__ void mma_tf32(float c[4], const unsigned a[4],
                                         const unsigned b[2])
{
    asm volatile(
        "mma.sync.aligned.m16n8k8.row.col.f32.tf32.tf32.f32 "
        "{%0,%1,%2,%3},{%4,%5,%6,%7},{%8,%9},{%0,%1,%2,%3};"
        : "+f"(c[0]), "+f"(c[1]), "+f"(c[2]), "+f"(c[3])
        : "r"(a[0]), "r"(a[1]), "r"(a[2]), "r"(a[3]), "r"(b[0]), "r"(b[1]));
}
__device__ __forceinline__ void cpa16(void* smem_dst, const void* gsrc)
{
    unsigned s = (unsigned)__cvta_generic_to_shared(smem_dst);
    asm volatile("cp.async.cg.shared.global [%0], [%1], 16;\n" :: "r"(s), "l"(gsrc));
}
#define CPC()  asm volatile("cp.async.commit_group;\n")
#define CPW1() asm volatile("cp.async.wait_group 1;\n")

// ---------------------------------------------------------------------------
// prepass: tf32-round x and weights (Wq also scaled by 1/8)
// ---------------------------------------------------------------------------
__global__ void prep_kernel(const float* __restrict__ x,
                            const float* __restrict__ Wq,
                            const float* __restrict__ Wk,
                            const float* __restrict__ Wv,
                            const float* __restrict__ Wo)
{
    const int sel = blockIdx.y;
    const float* src; float* dst; size_t n; float sc = 1.f;
    switch (sel) {
        case 0: src = x;  dst = g_X;               n = (size_t)MT * DM; break;
        case 1: src = Wq; dst = g_Wt;              n = (size_t)DM * DM; sc = 0.125f; break;
        case 2: src = Wk; dst = g_Wt + (size_t)DM*DM;   n = (size_t)DM * DM; break;
        case 3: src = Wv; dst = g_Wt + (size_t)2*DM*DM; n = (size_t)DM * DM; break;
        default:src = Wo; dst = g_Wt + (size_t)3*DM*DM; n = (size_t)DM * DM; break;
    }
    const size_t i = ((size_t)blockIdx.x * 256 + threadIdx.x) * 4;
    if (i < n) {
        float4 v = *(const float4*)&src[i];
        v.x = tfbits(v.x * sc); v.y = tfbits(v.y * sc);
        v.z = tfbits(v.z * sc); v.w = tfbits(v.w * sc);
        *(float4*)&dst[i] = v;
    }
}

// ---------------------------------------------------------------------------
// TF32 TC GEMM: C[M,N] = A[M,K] @ W[N,K]^T (+bias). Inputs already tf32.
// 128x128 tile, K-chunk 32, cp.async double-buffered. 8 warps, 64x32/warp.
// vt_out: write C transposed per-head ([b,h,d,s]) for the V projection.
// ---------------------------------------------------------------------------
#define KT 32
#define PAD 36
#define GSTG (128 * PAD)                 // floats per stage buffer (one matrix)
#define GEMM_SMEM_BYTES (4 * GSTG * 4)   // As[2] + Bs[2]

__device__ __forceinline__ void gemm_stage(float* As, float* Bs,
                                           const float* __restrict__ A,
                                           const float* __restrict__ W,
                                           int m0, int n0, int k0, int tid)
{
    const int lr = tid >> 3;
    const int lc = (tid & 7) * 4;
#pragma unroll
    for (int rep = 0; rep < 4; rep++) {
        const int row = lr + rep * 32;
        cpa16(&As[row * PAD + lc], &A[(size_t)(m0 + row) * DM + k0 + lc]);
        cpa16(&Bs[row * PAD + lc], &W[(size_t)(n0 + row) * DM + k0 + lc]);
    }
}

__device__ __forceinline__ void gemm128_tc(const float* __restrict__ A,
                                           const float* __restrict__ W,
                                           const float* __restrict__ bias,
                                           float* __restrict__ C,
                                           int vt_out)
{
    extern __shared__ float sm[];
    float* As = sm;                 // [2][128][PAD]
    float* Bs = sm + 2 * GSTG;      // [2][128][PAD]

    const int tid  = threadIdx.x;
    const int warp = tid >> 5, lane = tid & 31;
    const int wm = warp >> 2, wn = warp & 3;
    const int lg = lane >> 2, lt = lane & 3;
    const int m0 = blockIdx.y * 128;
    const int n0 = blockIdx.x * 128;

    float acc[4][4][4];
#pragma unroll
    for (int i = 0; i < 4; i++)
#pragma unroll
        for (int j = 0; j < 4; j++)
#pragma unroll
            for (int e = 0; e < 4; e++) acc[i][j][e] = 0.f;

    gemm_stage(As, Bs, A, W, m0, n0, 0, tid);
    CPC();

    for (int k0 = 0; k0 < DM; k0 += KT) {
        const int cur = (k0 >> 5) & 1;
        __syncthreads();   // readers of buffer cur^1 (iter-2) are done
        if (k0 + KT < DM)
            gemm_stage(As + (cur ^ 1) * GSTG, Bs + (cur ^ 1) * GSTG,
                       A, W, m0, n0, k0 + KT, tid);
        CPC();
        CPW1();
        __syncthreads();   // buffer cur visible

        const float* Ab = As + cur * GSTG;
        const float* Bb = Bs + cur * GSTG;
#pragma unroll
        for (int ks = 0; ks < 4; ks++) {
            unsigned a[4][4], b[4][2];
#pragma unroll
            for (int mt = 0; mt < 4; mt++) {
                const int r = wm * 64 + mt * 16 + lg;
                const int c = ks * 8 + lt;
                a[mt][0] = __float_as_uint(Ab[r * PAD + c]);
                a[mt][1] = __float_as_uint(Ab[(r + 8) * PAD + c]);
                a[mt][2] = __float_as_uint(Ab[r * PAD + c + 4]);
                a[mt][3] = __float_as_uint(Ab[(r + 8) * PAD + c + 4]);
            }
#pragma unroll
            for (int nt = 0; nt < 4; nt++) {
                const int r = wn * 32 + nt * 8 + lg;
                const int c = ks * 8 + lt;
                b[nt][0] = __float_as_uint(Bb[r * PAD + c]);
                b[nt][1] = __float_as_uint(Bb[r * PAD + c + 4]);
            }
#pragma unroll
            for (int mt = 0; mt < 4; mt++)
#pragma unroll
                for (int nt = 0; nt < 4; nt++)
                    mma_tf32(acc[mt][nt], a[mt], b[nt]);
        }
    }

    // epilogue
    if (!vt_out) {
#pragma unroll
        for (int mt = 0; mt < 4; mt++) {
            const int r0 = m0 + wm * 64 + mt * 16 + lg;
#pragma unroll
            for (int nt = 0; nt < 4; nt++) {
                const int col = n0 + wn * 32 + nt * 8 + 2 * lt;
                float b0 = 0.f, b1 = 0.f;
                if (bias) { b0 = bias[col]; b1 = bias[col + 1]; }
                float2 v0, v1;
                if (bias) {   // final output: full fp32
                    v0 = make_float2(acc[mt][nt][0] + b0, acc[mt][nt][1] + b1);
                    v1 = make_float2(acc[mt][nt][2] + b0, acc[mt][nt][3] + b1);
                } else {      // q/k scratch: tf32-round now
                    v0 = make_float2(tfbits(acc[mt][nt][0]), tfbits(acc[mt][nt][1]));
                    v1 = make_float2(tfbits(acc[mt][nt][2]), tfbits(acc[mt][nt][3]));
                }
                *(float2*)&C[(size_t)r0 * DM + col] = v0;
                *(float2*)&C[(size_t)(r0 + 8) * DM + col] = v1;
            }
        }
    } else {
        // V: write transposed per-head [b,h,d,s], tf32-rounded
#pragma unroll
        for (int mt = 0; mt < 4; mt++) {
            const int t0 = m0 + wm * 64 + mt * 16 + lg;     // token
#pragma unroll
            for (int nt = 0; nt < 4; nt++) {
                const int col = n0 + wn * 32 + nt * 8 + 2 * lt;
                const int h = col >> 6, d = col & 63;
#pragma unroll
                for (int e = 0; e < 4; e++) {
                    const int t = t0 + (e >> 1) * 8;
                    const int dd = d + (e & 1);
                    const int b = t >> 11, s = t & 2047;
                    C[((size_t)((b * NH + h) * HD + dd)) * SQ + s] =
                        tfbits(acc[mt][nt][e]);
                }
            }
        }
    }
}

__global__ __launch_bounds__(256, 2) void qkv_gemm_kernel()
{
    const float* W; float* C; int vt = 0;
    if (blockIdx.z == 0)      { W = g_Wt;                       C = g_Q; }
    else if (blockIdx.z == 1) { W = g_Wt + (size_t)DM*DM;       C = g_K; }
    else                      { W = g_Wt + (size_t)2*DM*DM;     C = g_Vt; vt = 1; }
    gemm128_tc(g_X, W, nullptr, C, vt);
}

__global__ __launch_bounds__(256, 2) void o_gemm_kernel(
    const float* __restrict__ bo, float* __restrict__ out)
{
    gemm128_tc(g_C, g_Wt + (size_t)3*DM*DM, bo, out, 0);
}

// ---------------------------------------------------------------------------
// Flash attention, TF32 TC, cp.async double-buffered K/V^T tiles.
// Block: 128 queries, 8 warps x 16 rows. Bias band hoisted to smem once.
// ---------------------------------------------------------------------------
#define APAD 68
#define ATILE (64 * APAD)                     // 4352 floats per K/V stage
#define KS_OFF 0
#define VT_OFF (2 * ATILE)                    // 8704
#define PS_OFF (4 * ATILE)                    // 17408
#define BS_OFF (PS_OFF + 128 * APAD)          // 26112
#define ATTN_SMEM_FLOATS (BS_OFF + 2176)      // 28288
#define ATTN_SMEM_BYTES  (ATTN_SMEM_FLOATS * 4)

__global__ __launch_bounds__(256, 2) void attn_kernel(const float* __restrict__ bt)
{
    extern __shared__ float sm[];
    float* Ks  = sm + KS_OFF;    // [2][64][APAD] key tiles (k, d)
    float* Vt  = sm + VT_OFF;    // [2][64][APAD] V^T tiles (d, kk)
    float* Ps  = sm + PS_OFF;    // [128][APAD] warp-local P (Q staging at init)
    float* bsA = sm + BS_OFF;    // [2175] bias band for this q-block

    const int tid  = threadIdx.x;
    const int warp = tid >> 5, lane = tid & 31;
    const int lg = lane >> 2, lt = lane & 3;
    const int bh = blockIdx.y;
    const int b = bh >> 4, h = bh & 15;
    const int q0 = blockIdx.x * 128;

    const float* gK = g_K  + (size_t)b * SQ * DM + h * HD;
    const float* gV = g_Vt + (size_t)(b * NH + h) * HD * SQ;

    // ---- bias band: rel indices [q0, q0+2174]
    for (int j = tid; j < 2175; j += 256) bsA[j] = bt[(size_t)(q0 + j) * NH + h];

    // ---- stage Q (already scaled+tf32) into Ps, pull fragments (warp-local)
    {
        const int r = tid >> 1;
        const int c0 = (tid & 1) * 32;
        const float* src = g_Q + (size_t)(b * SQ + q0 + r) * DM + h * HD;
#pragma unroll
        for (int rep = 0; rep < 8; rep++)
            *(float4*)&Ps[r * APAD + c0 + rep * 4] = *(const float4*)&src[c0 + rep * 4];
    }
    __syncwarp();
    unsigned qf[8][4];
    {
        const int r = warp * 16 + lg;
#pragma unroll
        for (int ks = 0; ks < 8; ks++) {
            const int c = ks * 8 + lt;
            qf[ks][0] = __float_as_uint(Ps[r * APAD + c]);
            qf[ks][1] = __float_as_uint(Ps[(r + 8) * APAD + c]);
            qf[ks][2] = __float_as_uint(Ps[r * APAD + c + 4]);
            qf[ks][3] = __float_as_uint(Ps[(r + 8) * APAD + c + 4]);
        }
    }
    __syncwarp();

    // ---- prefetch tile 0
    {
#pragma unroll
        for (int rep = 0; rep < 4; rep++) {
            const int f4 = tid + rep * 256;
            const int r = f4 >> 4, c = (f4 & 15) * 4;
            cpa16(&Ks[r * APAD + c], &gK[(size_t)r * DM + c]);
            cpa16(&Vt[r * APAD + c], &gV[(size_t)r * SQ + c]);
        }
        CPC();
    }

    const int r0 = warp * 16 + lg;
    const int r1 = r0 + 8;
    float m0v = -1e30f, m1v = -1e30f, l0v = 0.f, l1v = 0.f;
    float o[8][4];
#pragma unroll
    for (int nt = 0; nt < 8; nt++)
#pragma unroll
        for (int e = 0; e < 4; e++) o[nt][e] = 0.f;

    for (int k0 = 0, t = 0; k0 < SQ; k0 += 64, t++) {
        const int cur = t & 1;
        __syncthreads();   // readers of buffer cur^1 (iter t-1) done; publishes bsA at t=0
        if (k0 + 64 < SQ) {
            float* Kn = Ks + (cur ^ 1) * ATILE;
            float* Vn = Vt + (cur ^ 1) * ATILE;
#pragma unroll
            for (int rep = 0; rep < 4; rep++) {
                const int f4 = tid + rep * 256;
                const int r = f4 >> 4, c = (f4 & 15) * 4;
                cpa16(&Kn[r * APAD + c], &gK[(size_t)(k0 + 64 + r) * DM + c]);
                cpa16(&Vn[r * APAD + c], &gV[(size_t)r * SQ + k0 + 64 + c]);
            }
        }
        CPC();
        CPW1();
        __syncthreads();   // tile t visible

        const float* Kb = Ks + cur * ATILE;
        const float* Vb = Vt + cur * ATILE;

        // ---- S = (Q/8) @ K^T
        float s[8][4];
#pragma unroll
        for (int nt = 0; nt < 8; nt++)
#pragma unroll
            for (int e = 0; e < 4; e++) s[nt][e] = 0.f;
#pragma unroll
        for (int ks = 0; ks < 8; ks++) {
            const int c = ks * 8 + lt;
#pragma unroll
            for (int nt = 0; nt < 8; nt++) {
                unsigned bf[2];
                const int n = nt * 8 + lg;
                bf[0] = __float_as_uint(Kb[n * APAD + c]);
                bf[1] = __float_as_uint(Kb[n * APAD + c + 4]);
                mma_tf32(s[nt], qf[ks], bf);
            }
        }

        // ---- bias + online softmax
        const int jb0 = r0 + 2047 - k0;
        const int jb1 = r1 + 2047 - k0;
        float mx0 = -1e30f, mx1 = -1e30f;
#pragma unroll
        for (int nt = 0; nt < 8; nt++) {
            const int col = nt * 8 + 2 * lt;
            s[nt][0] += bsA[jb0 - col];
            s[nt][1] += bsA[jb0 - col - 1];
            s[nt][2] += bsA[jb1 - col];
            s[nt][3] += bsA[jb1 - col - 1];
            mx0 = fmaxf(mx0, fmaxf(s[nt][0], s[nt][1]));
            mx1 = fmaxf(mx1, fmaxf(s[nt][2], s[nt][3]));
        }
#pragma unroll
        for (int off = 1; off <= 2; off <<= 1) {
            mx0 = fmaxf(mx0, __shfl_xor_sync(0xffffffffu, mx0, off));
            mx1 = fmaxf(mx1, __shfl_xor_sync(0xffffffffu, mx1, off));
        }
        const float mn0 = fmaxf(m0v, mx0);
        const float mn1 = fmaxf(m1v, mx1);
        const float cr0 = __expf(m0v - mn0);
        const float cr1 = __expf(m1v - mn1);
        float sum0 = 0.f, sum1 = 0.f;
#pragma unroll
        for (int nt = 0; nt < 8; nt++) {
            s[nt][0] = __expf(s[nt][0] - mn0);
            s[nt][1] = __expf(s[nt][1] - mn0);
            s[nt][2] = __expf(s[nt][2] - mn1);
            s[nt][3] = __expf(s[nt][3] - mn1);
            sum0 += s[nt][0] + s[nt][1];
            sum1 += s[nt][2] + s[nt][3];
            const int col = nt * 8 + 2 * lt;
            *(float2*)&Ps[r0 * APAD + col] =
                make_float2(tfbits(s[nt][0]), tfbits(s[nt][1]));
            *(float2*)&Ps[r1 * APAD + col] =
                make_float2(tfbits(s[nt][2]), tfbits(s[nt][3]));
        }
#pragma unroll
        for (int off = 1; off <= 2; off <<= 1) {
            sum0 += __shfl_xor_sync(0xffffffffu, sum0, off);
            sum1 += __shfl_xor_sync(0xffffffffu, sum1, off);
        }
        l0v = l0v * cr0 + sum0;
        l1v = l1v * cr1 + sum1;
        m0v = mn0; m1v = mn1;
#pragma unroll
        for (int nt = 0; nt < 8; nt++) {
            o[nt][0] *= cr0; o[nt][1] *= cr0;
            o[nt][2] *= cr1; o[nt][3] *= cr1;
        }
        __syncwarp();

        // ---- acc += P @ V
#pragma unroll
        for (int ks = 0; ks < 8; ks++) {
            unsigned pa[4];
            const int c = ks * 8 + lt;
            pa[0] = __float_as_uint(Ps[r0 * APAD + c]);
            pa[1] = __float_as_uint(Ps[r1 * APAD + c]);
            pa[2] = __float_as_uint(Ps[r0 * APAD + c + 4]);
            pa[3] = __float_as_uint(Ps[r1 * APAD + c + 4]);
#pragma unroll
            for (int nt = 0; nt < 8; nt++) {
                unsigned bf[2];
                const int n = nt * 8 + lg;
                bf[0] = __float_as_uint(Vb[n * APAD + c]);
                bf[1] = __float_as_uint(Vb[n * APAD + c + 4]);
                mma_tf32(o[nt], pa, bf);
            }
        }
    }

    // ---- normalize + write ctx [B,S,D] (tf32 for the O projection)
    const float inv0 = 1.f / l0v;
    const float inv1 = 1.f / l1v;
    float* dst0 = g_C + (size_t)(b * SQ + q0 + r0) * DM + h * HD;
    float* dst1 = g_C + (size_t)(b * SQ + q0 + r1) * DM + h * HD;
#pragma unroll
    for (int nt = 0; nt < 8; nt++) {
        const int col = nt * 8 + 2 * lt;
        *(float2*)&dst0[col] = make_float2(tfbits(o[nt][0] * inv0),
                                           tfbits(o[nt][1] * inv0));
        *(float2*)&dst1[col] = make_float2(tfbits(o[nt][2] * inv1),
                                           tfbits(o[nt][3] * inv1));
    }
}

// ---------------------------------------------------------------------------
extern "C" void kernel_launch(void* const* d_in, const int* in_sizes, int n_in,
                              void* d_out, int out_size)
{
    (void)in_sizes; (void)n_in; (void)out_size;
    const float* x   = (const float*)d_in[0];
    const float* Wq  = (const float*)d_in[1];
    const float* Wk  = (const float*)d_in[2];
    const float* Wv  = (const float*)d_in[3];
    const float* Wo  = (const float*)d_in[4];
    const float* bo  = (const float*)d_in[5];
    const float* bt  = (const float*)d_in[6];
    float* out = (float*)d_out;

    // 0) tf32 prepass
    dim3 g0((MT * DM / 4 + 255) / 256, 5);
    prep_kernel<<<g0, 256>>>(x, Wq, Wk, Wv, Wo);

    // 1) QKV projections
    cudaFuncSetAttribute(qkv_gemm_kernel,
                         cudaFuncAttributeMaxDynamicSharedMemorySize,
                         GEMM_SMEM_BYTES);
    dim3 g1(DM / 128, MT / 128, 3);
    qkv_gemm_kernel<<<g1, 256, GEMM_SMEM_BYTES>>>();

    // 2) attention
    cudaFuncSetAttribute(attn_kernel,
                         cudaFuncAttributeMaxDynamicSharedMemorySize,
                         ATTN_SMEM_BYTES);
    dim3 g2(SQ / 128, BB * NH);
    attn_kernel<<<g2, 256, ATTN_SMEM_BYTES>>>(bt);

    // 3) output projection + bias
    cudaFuncSetAttribute(o_gemm_kernel,
                         cudaFuncAttributeMaxDynamicSharedMemorySize,
                         GEMM_SMEM_BYTES);
    dim3 g3(DM / 128, MT / 128);
    o_gemm_kernel<<<g3, 256, GEMM_SMEM_BYTES>>>(bo, out);
}

// round 7
// speedup vs baseline: 4.0729x; 1.1230x over previous
#include <cuda_runtime.h>
#include <cstdint>

#define DM 1024
#define NH 16
#define HD 64
#define SQ 2048
#define BB 4
#define MT (BB*SQ)   // 8192 rows total

// Scratch (no allocations allowed -> __device__ globals).
__device__ float g_X [(size_t)MT * DM];          // x, tf32
__device__ float g_Wt[(size_t)4 * DM * DM];      // Wq*log2e/8, Wk, Wv, Wo (tf32)
__device__ float g_Q [(size_t)MT * DM];          // q*log2e/8, tf32
__device__ float g_K [(size_t)MT * DM];          // k, tf32
__device__ float g_Vt[(size_t)MT * DM];          // v^T per (b,h): [64][SQ], tf32
__device__ float g_C [(size_t)MT * DM];          // ctx, tf32

#define LOG2E 1.4426950408889634f

// ---------------------------------------------------------------------------
// helpers
// ---------------------------------------------------------------------------
__device__ __forceinline__ float tfbits(float f)
{
    unsigned u;
    asm("cvt.rna.tf32.f32 %0, %1;" : "=r"(u) : "f"(f));
    return __uint_as_float(u);
}
__device__ __forceinline__ float ex2(float x)
{
    float y;
    asm("ex2.approx.ftz.f32 %0, %1;" : "=f"(y) : "f"(x));
    return y;
}
__device__ __forceinline__ void mma_tf32(float c[4], const unsigned a[4],
                                         const unsigned b[2])
{
    asm volatile(
        "mma.sync.aligned.m16n8k8.row.col.f32.tf32.tf32.f32 "
        "{%0,%1,%2,%3},{%4,%5,%6,%7},{%8,%9},{%0,%1,%2,%3};"
        : "+f"(c[0]), "+f"(c[1]), "+f"(c[2]), "+f"(c[3])
        : "r"(a[0]), "r"(a[1]), "r"(a[2]), "r"(a[3]), "r"(b[0]), "r"(b[1]));
}
__device__ __forceinline__ void cpa16(void* smem_dst, const void* gsrc)
{
    unsigned s = (unsigned)__cvta_generic_to_shared(smem_dst);
    asm volatile("cp.async.cg.shared.global [%0], [%1], 16;\n" :: "r"(s), "l"(gsrc));
}
#define CPC()  asm volatile("cp.async.commit_group;\n")
#define CPW1() asm volatile("cp.async.wait_group 1;\n")

// ---------------------------------------------------------------------------
// prepass: tf32-round x and weights (Wq scaled by log2e/8)
// ---------------------------------------------------------------------------
__global__ void prep_kernel(const float* __restrict__ x,
                            const float* __restrict__ Wq,
                            const float* __restrict__ Wk,
                            const float* __restrict__ Wv,
                            const float* __restrict__ Wo)
{
    const int sel = blockIdx.y;
    const float* src; float* dst; size_t n; float sc = 1.f;
    switch (sel) {
        case 0: src = x;  dst = g_X;               n = (size_t)MT * DM; break;
        case 1: src = Wq; dst = g_Wt;              n = (size_t)DM * DM;
                sc = 0.125f * LOG2E; break;
        case 2: src = Wk; dst = g_Wt + (size_t)DM*DM;   n = (size_t)DM * DM; break;
        case 3: src = Wv; dst = g_Wt + (size_t)2*DM*DM; n = (size_t)DM * DM; break;
        default:src = Wo; dst = g_Wt + (size_t)3*DM*DM; n = (size_t)DM * DM; break;
    }
    const size_t i = ((size_t)blockIdx.x * 256 + threadIdx.x) * 4;
    if (i < n) {
        float4 v = *(const float4*)&src[i];
        v.x = tfbits(v.x * sc); v.y = tfbits(v.y * sc);
        v.z = tfbits(v.z * sc); v.w = tfbits(v.w * sc);
        *(float4*)&dst[i] = v;
    }
}

// ---------------------------------------------------------------------------
// TF32 TC GEMM: C[M,N] = A[M,K] @ W[N,K]^T (+bias). Inputs already tf32.
// 128x128 tile, K-chunk 32, cp.async double-buffered.
// 4 warps, 64x64 per warp (2x2 warp grid) -> high fragment reuse.
// mode: 0 = tf32 out (q/k), 1 = fp32 + bias (final), 2 = per-head transposed V
// ---------------------------------------------------------------------------
#define KT 32
#define PAD 36
#define GSTG (128 * PAD)
#define GEMM_SMEM_BYTES (4 * GSTG * 4)   // As[2] + Bs[2] = 73728 B

__device__ __forceinline__ void gemm_stage(float* As, float* Bs,
                                           const float* __restrict__ A,
                                           const float* __restrict__ W,
                                           int m0, int n0, int k0, int tid)
{
#pragma unroll
    for (int rep = 0; rep < 8; rep++) {
        const int f4 = tid + rep * 128;     // 0..1023
        const int row = f4 >> 3;
        const int c4 = (f4 & 7) * 4;
        cpa16(&As[row * PAD + c4], &A[(size_t)(m0 + row) * DM + k0 + c4]);
        cpa16(&Bs[row * PAD + c4], &W[(size_t)(n0 + row) * DM + k0 + c4]);
    }
}

__device__ __forceinline__ void gemm128_tc(const float* __restrict__ A,
                                           const float* __restrict__ W,
                                           const float* __restrict__ bias,
                                           float* __restrict__ C,
                                           int mode)
{
    extern __shared__ float smg[];
    float* As = smg;                 // [2][128][PAD]
    float* Bs = smg + 2 * GSTG;      // [2][128][PAD]

    const int tid  = threadIdx.x;
    const int warp = tid >> 5, lane = tid & 31;
    const int wm = warp >> 1, wn = warp & 1;
    const int lg = lane >> 2, lt = lane & 3;
    const int m0 = blockIdx.y * 128;
    const int n0 = blockIdx.x * 128;

    float acc[4][8][4];
#pragma unroll
    for (int i = 0; i < 4; i++)
#pragma unroll
        for (int j = 0; j < 8; j++)
#pragma unroll
            for (int e = 0; e < 4; e++) acc[i][j][e] = 0.f;

    gemm_stage(As, Bs, A, W, m0, n0, 0, tid);
    CPC();

    for (int k0 = 0; k0 < DM; k0 += KT) {
        const int cur = (k0 >> 5) & 1;
        __syncthreads();
        if (k0 + KT < DM)
            gemm_stage(As + (cur ^ 1) * GSTG, Bs + (cur ^ 1) * GSTG,
                       A, W, m0, n0, k0 + KT, tid);
        CPC();
        CPW1();
        __syncthreads();

        const float* Ab = As + cur * GSTG;
        const float* Bb = Bs + cur * GSTG;
#pragma unroll
        for (int ks = 0; ks < 4; ks++) {
            unsigned a[4][4], b[8][2];
            const int c = ks * 8 + lt;
#pragma unroll
            for (int mt = 0; mt < 4; mt++) {
                const int r = wm * 64 + mt * 16 + lg;
                a[mt][0] = __float_as_uint(Ab[r * PAD + c]);
                a[mt][1] = __float_as_uint(Ab[(r + 8) * PAD + c]);
                a[mt][2] = __float_as_uint(Ab[r * PAD + c + 4]);
                a[mt][3] = __float_as_uint(Ab[(r + 8) * PAD + c + 4]);
            }
#pragma unroll
            for (int nt = 0; nt < 8; nt++) {
                const int n = wn * 64 + nt * 8 + lg;
                b[nt][0] = __float_as_uint(Bb[n * PAD + c]);
                b[nt][1] = __float_as_uint(Bb[n * PAD + c + 4]);
            }
#pragma unroll
            for (int mt = 0; mt < 4; mt++)
#pragma unroll
                for (int nt = 0; nt < 8; nt++)
                    mma_tf32(acc[mt][nt], a[mt], b[nt]);
        }
    }

    // epilogue
    if (mode != 2) {
#pragma unroll
        for (int mt = 0; mt < 4; mt++) {
            const int r0 = m0 + wm * 64 + mt * 16 + lg;
#pragma unroll
            for (int nt = 0; nt < 8; nt++) {
                const int col = n0 + wn * 64 + nt * 8 + 2 * lt;
                float2 v0, v1;
                if (mode == 1) {
                    const float b0 = bias[col], b1 = bias[col + 1];
                    v0 = make_float2(acc[mt][nt][0] + b0, acc[mt][nt][1] + b1);
                    v1 = make_float2(acc[mt][nt][2] + b0, acc[mt][nt][3] + b1);
                } else {
                    v0 = make_float2(tfbits(acc[mt][nt][0]), tfbits(acc[mt][nt][1]));
                    v1 = make_float2(tfbits(acc[mt][nt][2]), tfbits(acc[mt][nt][3]));
                }
                *(float2*)&C[(size_t)r0 * DM + col] = v0;
                *(float2*)&C[(size_t)(r0 + 8) * DM + col] = v1;
            }
        }
    } else {
        // V: write transposed per-head [b,h,d,s], tf32-rounded
#pragma unroll
        for (int mt = 0; mt < 4; mt++) {
            const int t0 = m0 + wm * 64 + mt * 16 + lg;
#pragma unroll
            for (int nt = 0; nt < 8; nt++) {
                const int col = n0 + wn * 64 + nt * 8 + 2 * lt;
                const int h = col >> 6, d = col & 63;
#pragma unroll
                for (int e = 0; e < 4; e++) {
                    const int t = t0 + (e >> 1) * 8;
                    const int dd = d + (e & 1);
                    const int b = t >> 11, s = t & 2047;
                    C[((size_t)(b * NH + h) * HD + dd) * SQ + s] =
                        tfbits(acc[mt][nt][e]);
                }
            }
        }
    }
}

__global__ __launch_bounds__(128, 2) void qkv_gemm_kernel()
{
    const float* W; float* C; int mode;
    if (blockIdx.z == 0)      { W = g_Wt;                   C = g_Q;  mode = 0; }
    else if (blockIdx.z == 1) { W = g_Wt + (size_t)DM*DM;   C = g_K;  mode = 0; }
    else                      { W = g_Wt + (size_t)2*DM*DM; C = g_Vt; mode = 2; }
    gemm128_tc(g_X, W, nullptr, C, mode);
}

__global__ __launch_bounds__(128, 2) void o_gemm_kernel(
    const float* __restrict__ bo, float* __restrict__ out)
{
    gemm128_tc(g_C, g_Wt + (size_t)3*DM*DM, bo, out, 1);
}

// ---------------------------------------------------------------------------
// Flash attention, TF32 TC, cp.async double-buffered K/V^T tiles.
// 128 queries per CTA, 4 warps x 32 query rows (2 m-tiles per warp).
// Softmax in log2 domain (scale folded into Q and bias) -> raw ex2.
// ---------------------------------------------------------------------------
#define APAD 68
#define ATILE (64 * APAD)
#define KS_OFF 0
#define VT_OFF (2 * ATILE)
#define PS_OFF (4 * ATILE)
#define BS_OFF (PS_OFF + 128 * APAD)
#define ATTN_SMEM_FLOATS (BS_OFF + 2176)
#define ATTN_SMEM_BYTES  (ATTN_SMEM_FLOATS * 4)

__global__ __launch_bounds__(128, 2) void attn_kernel(const float* __restrict__ bt)
{
    extern __shared__ float sm[];
    float* Ks  = sm + KS_OFF;    // [2][64][APAD] key tiles (k, d)
    float* Vt  = sm + VT_OFF;    // [2][64][APAD] V^T tiles (d, kk)
    float* Ps  = sm + PS_OFF;    // [128][APAD] P staging (Q staging at init)
    float* bsA = sm + BS_OFF;    // [2175] bias band (log2 domain)

    const int tid  = threadIdx.x;
    const int warp = tid >> 5, lane = tid & 31;
    const int lg = lane >> 2, lt = lane & 3;
    const int bh = blockIdx.y;
    const int b = bh >> 4, h = bh & 15;
    const int q0 = blockIdx.x * 128;

    const float* gK = g_K  + (size_t)b * SQ * DM + h * HD;
    const float* gV = g_Vt + (size_t)(b * NH + h) * HD * SQ;

    // bias band in log2 domain
    for (int j = tid; j < 2175; j += 128)
        bsA[j] = bt[(size_t)(q0 + j) * NH + h] * LOG2E;

    // stage Q rows (already scaled + tf32): thread tid owns row tid
    {
        const float* src = g_Q + (size_t)(b * SQ + q0 + tid) * DM + h * HD;
#pragma unroll
        for (int rep = 0; rep < 16; rep++)
            *(float4*)&Ps[tid * APAD + rep * 4] = *(const float4*)&src[rep * 4];
    }
    __syncwarp();   // warp w reads rows w*32..w*32+31, staged by its own threads

    // persistent Q fragments: 2 m-tiles x 8 k-steps
    unsigned qf[2][8][4];
#pragma unroll
    for (int mt = 0; mt < 2; mt++) {
        const int r = warp * 32 + mt * 16 + lg;
#pragma unroll
        for (int ks = 0; ks < 8; ks++) {
            const int c = ks * 8 + lt;
            qf[mt][ks][0] = __float_as_uint(Ps[r * APAD + c]);
            qf[mt][ks][1] = __float_as_uint(Ps[(r + 8) * APAD + c]);
            qf[mt][ks][2] = __float_as_uint(Ps[r * APAD + c + 4]);
            qf[mt][ks][3] = __float_as_uint(Ps[(r + 8) * APAD + c + 4]);
        }
    }
    __syncwarp();

    // prefetch tile 0
    {
#pragma unroll
        for (int rep = 0; rep < 8; rep++) {
            const int f4 = tid + rep * 128;
            const int r = f4 >> 4, c = (f4 & 15) * 4;
            cpa16(&Ks[r * APAD + c], &gK[(size_t)r * DM + c]);
            cpa16(&Vt[r * APAD + c], &gV[(size_t)r * SQ + c]);
        }
        CPC();
    }

    // per-thread rows: mt in {0,1}, halves A (rows +0) and B (rows +8)
    float mA[2] = {-1e30f, -1e30f}, mB[2] = {-1e30f, -1e30f};
    float lA[2] = {0.f, 0.f},       lB[2] = {0.f, 0.f};
    float o[2][8][4];
#pragma unroll
    for (int mt = 0; mt < 2; mt++)
#pragma unroll
        for (int nt = 0; nt < 8; nt++)
#pragma unroll
            for (int e = 0; e < 4; e++) o[mt][nt][e] = 0.f;

    for (int k0 = 0, t = 0; k0 < SQ; k0 += 64, t++) {
        const int cur = t & 1;
        __syncthreads();
        if (k0 + 64 < SQ) {
            float* Kn = Ks + (cur ^ 1) * ATILE;
            float* Vn = Vt + (cur ^ 1) * ATILE;
#pragma unroll
            for (int rep = 0; rep < 8; rep++) {
                const int f4 = tid + rep * 128;
                const int r = f4 >> 4, c = (f4 & 15) * 4;
                cpa16(&Kn[r * APAD + c], &gK[(size_t)(k0 + 64 + r) * DM + c]);
                cpa16(&Vn[r * APAD + c], &gV[(size_t)r * SQ + k0 + 64 + c]);
            }
        }
        CPC();
        CPW1();
        __syncthreads();

        const float* Kb = Ks + cur * ATILE;
        const float* Vb = Vt + cur * ATILE;

        // ---- S = Q' @ K^T  (log2 domain)
        float s[2][8][4];
#pragma unroll
        for (int mt = 0; mt < 2; mt++)
#pragma unroll
            for (int nt = 0; nt < 8; nt++)
#pragma unroll
                for (int e = 0; e < 4; e++) s[mt][nt][e] = 0.f;
#pragma unroll
        for (int ks = 0; ks < 8; ks++) {
            const int c = ks * 8 + lt;
#pragma unroll
            for (int nt = 0; nt < 8; nt++) {
                unsigned bf[2];
                const int n = nt * 8 + lg;
                bf[0] = __float_as_uint(Kb[n * APAD + c]);
                bf[1] = __float_as_uint(Kb[n * APAD + c + 4]);
                mma_tf32(s[0][nt], qf[0][ks], bf);
                mma_tf32(s[1][nt], qf[1][ks], bf);
            }
        }

        // ---- bias + online softmax (4 rows per thread, 4-lane reductions)
#pragma unroll
        for (int mt = 0; mt < 2; mt++) {
            const int rA = warp * 32 + mt * 16 + lg;
            const int rB = rA + 8;
            const int jbA = rA + 2047 - k0;
            const int jbB = rB + 2047 - k0;
            float mxA = -1e30f, mxB = -1e30f;
#pragma unroll
            for (int nt = 0; nt < 8; nt++) {
                const int col = nt * 8 + 2 * lt;
                s[mt][nt][0] += bsA[jbA - col];
                s[mt][nt][1] += bsA[jbA - col - 1];
                s[mt][nt][2] += bsA[jbB - col];
                s[mt][nt][3] += bsA[jbB - col - 1];
                mxA = fmaxf(mxA, fmaxf(s[mt][nt][0], s[mt][nt][1]));
                mxB = fmaxf(mxB, fmaxf(s[mt][nt][2], s[mt][nt][3]));
            }
#pragma unroll
            for (int off = 1; off <= 2; off <<= 1) {
                mxA = fmaxf(mxA, __shfl_xor_sync(0xffffffffu, mxA, off));
                mxB = fmaxf(mxB, __shfl_xor_sync(0xffffffffu, mxB, off));
            }
            const float mnA = fmaxf(mA[mt], mxA);
            const float mnB = fmaxf(mB[mt], mxB);
            const float crA = ex2(mA[mt] - mnA);
            const float crB = ex2(mB[mt] - mnB);
            float sA = 0.f, sB = 0.f;
#pragma unroll
            for (int nt = 0; nt < 8; nt++) {
                s[mt][nt][0] = ex2(s[mt][nt][0] - mnA);
                s[mt][nt][1] = ex2(s[mt][nt][1] - mnA);
                s[mt][nt][2] = ex2(s[mt][nt][2] - mnB);
                s[mt][nt][3] = ex2(s[mt][nt][3] - mnB);
                sA += s[mt][nt][0] + s[mt][nt][1];
                sB += s[mt][nt][2] + s[mt][nt][3];
                const int col = nt * 8 + 2 * lt;
                *(float2*)&Ps[rA * APAD + col] =
                    make_float2(tfbits(s[mt][nt][0]), tfbits(s[mt][nt][1]));
                *(float2*)&Ps[rB * APAD + col] =
                    make_float2(tfbits(s[mt][nt][2]), tfbits(s[mt][nt][3]));
            }
#pragma unroll
            for (int off = 1; off <= 2; off <<= 1) {
                sA += __shfl_xor_sync(0xffffffffu, sA, off);
                sB += __shfl_xor_sync(0xffffffffu, sB, off);
            }
            lA[mt] = lA[mt] * crA + sA;
            lB[mt] = lB[mt] * crB + sB;
            mA[mt] = mnA; mB[mt] = mnB;
#pragma unroll
            for (int nt = 0; nt < 8; nt++) {
                o[mt][nt][0] *= crA; o[mt][nt][1] *= crA;
                o[mt][nt][2] *= crB; o[mt][nt][3] *= crB;
            }
        }
        __syncwarp();   // P rows visible within warp

        // ---- acc += P @ V
#pragma unroll
        for (int ks = 0; ks < 8; ks++) {
            const int c = ks * 8 + lt;
            unsigned pa[2][4];
#pragma unroll
            for (int mt = 0; mt < 2; mt++) {
                const int rA = warp * 32 + mt * 16 + lg;
                pa[mt][0] = __float_as_uint(Ps[rA * APAD + c]);
                pa[mt][1] = __float_as_uint(Ps[(rA + 8) * APAD + c]);
                pa[mt][2] = __float_as_uint(Ps[rA * APAD + c + 4]);
                pa[mt][3] = __float_as_uint(Ps[(rA + 8) * APAD + c + 4]);
            }
#pragma unroll
            for (int nt = 0; nt < 8; nt++) {
                unsigned bf[2];
                const int n = nt * 8 + lg;
                bf[0] = __float_as_uint(Vb[n * APAD + c]);
                bf[1] = __float_as_uint(Vb[n * APAD + c + 4]);
                mma_tf32(o[0][nt], pa[0], bf);
                mma_tf32(o[1][nt], pa[1], bf);
            }
        }
    }

    // ---- normalize + write ctx [B,S,D] (tf32 for the O projection)
#pragma unroll
    for (int mt = 0; mt < 2; mt++) {
        const int rA = warp * 32 + mt * 16 + lg;
        const float invA = 1.f / lA[mt];
        const float invB = 1.f / lB[mt];
        float* dstA = g_C + (size_t)(b * SQ + q0 + rA) * DM + h * HD;
        float* dstB = g_C + (size_t)(b * SQ + q0 + rA + 8) * DM + h * HD;
#pragma unroll
        for (int nt = 0; nt < 8; nt++) {
            const int col = nt * 8 + 2 * lt;
            *(float2*)&dstA[col] = make_float2(tfbits(o[mt][nt][0] * invA),
                                               tfbits(o[mt][nt][1] * invA));
            *(float2*)&dstB[col] = make_float2(tfbits(o[mt][nt][2] * invB),
                                               tfbits(o[mt][nt][3] * invB));
        }
    }
}

// ---------------------------------------------------------------------------
extern "C" void kernel_launch(void* const* d_in, const int* in_sizes, int n_in,
                              void* d_out, int out_size)
{
    (void)in_sizes; (void)n_in; (void)out_size;
    const float* x   = (const float*)d_in[0];
    const float* Wq  = (const float*)d_in[1];
    const float* Wk  = (const float*)d_in[2];
    const float* Wv  = (const float*)d_in[3];
    const float* Wo  = (const float*)d_in[4];
    const float* bo  = (const float*)d_in[5];
    const float* bt  = (const float*)d_in[6];
    float* out = (float*)d_out;

    // 0) tf32 prepass
    dim3 g0((MT * DM / 4 + 255) / 256, 5);
    prep_kernel<<<g0, 256>>>(x, Wq, Wk, Wv, Wo);

    // 1) QKV projections
    cudaFuncSetAttribute(qkv_gemm_kernel,
                         cudaFuncAttributeMaxDynamicSharedMemorySize,
                         GEMM_SMEM_BYTES);
    dim3 g1(DM / 128, MT / 128, 3);
    qkv_gemm_kernel<<<g1, 128, GEMM_SMEM_BYTES>>>();

    // 2) attention
    cudaFuncSetAttribute(attn_kernel,
                         cudaFuncAttributeMaxDynamicSharedMemorySize,
                         ATTN_SMEM_BYTES);
    dim3 g2(SQ / 128, BB * NH);
    attn_kernel<<<g2, 128, ATTN_SMEM_BYTES>>>(bt);

    // 3) output projection + bias
    cudaFuncSetAttribute(o_gemm_kernel,
                         cudaFuncAttributeMaxDynamicSharedMemorySize,
                         GEMM_SMEM_BYTES);
    dim3 g3(DM / 128, MT / 128);
    o_gemm_kernel<<<g3, 128, GEMM_SMEM_BYTES>>>(bo, out);
}

// round 8
// speedup vs baseline: 6.9530x; 1.7071x over previous
#include <cuda_runtime.h>
#include <cuda_fp16.h>
#include <cstdint>

#define DM 1024
#define NH 16
#define HD 64
#define SQ 2048
#define BB 4
#define MT (BB*SQ)   // 8192 rows total

// Scratch (no allocations allowed -> __device__ globals). All fp16 now.
__device__ __half g_X [(size_t)MT * DM];
__device__ __half g_Wt[(size_t)4 * DM * DM];     // Wq*log2e/8, Wk, Wv, Wo
__device__ __half g_Q [(size_t)MT * DM];         // q*log2e/8
__device__ __half g_K [(size_t)MT * DM];
__device__ __half g_Vt[(size_t)MT * DM];         // v^T per (b,h): [64][SQ]
__device__ __half g_C [(size_t)MT * DM];         // ctx

#define LOG2E 1.4426950408889634f

// ---------------------------------------------------------------------------
// helpers
// ---------------------------------------------------------------------------
__device__ __forceinline__ float ex2(float x)
{
    float y;
    asm("ex2.approx.ftz.f32 %0, %1;" : "=f"(y) : "f"(x));
    return y;
}
__device__ __forceinline__ void mma_f16(float c[4], const unsigned a[4],
                                        const unsigned b[2])
{
    asm volatile(
        "mma.sync.aligned.m16n8k16.row.col.f32.f16.f16.f32 "
        "{%0,%1,%2,%3},{%4,%5,%6,%7},{%8,%9},{%0,%1,%2,%3};"
        : "+f"(c[0]), "+f"(c[1]), "+f"(c[2]), "+f"(c[3])
        : "r"(a[0]), "r"(a[1]), "r"(a[2]), "r"(a[3]), "r"(b[0]), "r"(b[1]));
}
__device__ __forceinline__ void cpa16(void* smem_dst, const void* gsrc)
{
    unsigned s = (unsigned)__cvta_generic_to_shared(smem_dst);
    asm volatile("cp.async.cg.shared.global [%0], [%1], 16;\n" :: "r"(s), "l"(gsrc));
}
#define CPC()  asm volatile("cp.async.commit_group;\n")
#define CPW1() asm volatile("cp.async.wait_group 1;\n")
__device__ __forceinline__ unsigned ldh2(const __half* p)
{
    return *(const unsigned*)p;
}

// ---------------------------------------------------------------------------
// prepass: fp32 -> fp16 (Wq scaled by log2e/8)
// ---------------------------------------------------------------------------
__global__ void prep_kernel(const float* __restrict__ x,
                            const float* __restrict__ Wq,
                            const float* __restrict__ Wk,
                            const float* __restrict__ Wv,
                            const float* __restrict__ Wo)
{
    const int sel = blockIdx.y;
    const float* src; __half* dst; size_t n; float sc = 1.f;
    switch (sel) {
        case 0: src = x;  dst = g_X;               n = (size_t)MT * DM; break;
        case 1: src = Wq; dst = g_Wt;              n = (size_t)DM * DM;
                sc = 0.125f * LOG2E; break;
        case 2: src = Wk; dst = g_Wt + (size_t)DM*DM;   n = (size_t)DM * DM; break;
        case 3: src = Wv; dst = g_Wt + (size_t)2*DM*DM; n = (size_t)DM * DM; break;
        default:src = Wo; dst = g_Wt + (size_t)3*DM*DM; n = (size_t)DM * DM; break;
    }
    const size_t i = ((size_t)blockIdx.x * 256 + threadIdx.x) * 4;
    if (i < n) {
        float4 v = *(const float4*)&src[i];
        __half2 h0 = __floats2half2_rn(v.x * sc, v.y * sc);
        __half2 h1 = __floats2half2_rn(v.z * sc, v.w * sc);
        *(__half2*)&dst[i]     = h0;
        *(__half2*)&dst[i + 2] = h1;
    }
}

// ---------------------------------------------------------------------------
// FP16 TC GEMM: C[M,N] = A[M,K] @ W[N,K]^T (+bias), fp32 accum.
// 128x128 tile, K-chunk 64 halves, cp.async double-buffered.
// 4 warps, 64x64 per warp. smem rows padded to 80 halves (conflict-free).
// mode: 0 = fp16 out (q/k), 1 = fp32 + bias (final), 2 = per-head transposed V
// ---------------------------------------------------------------------------
#define KT 64
#define PAD 80
#define GSTG (128 * PAD)                      // halves per matrix stage
#define GEMM_SMEM_BYTES (4 * GSTG * 2)        // 81920 B

__device__ __forceinline__ void gemm_stage(__half* As, __half* Bs,
                                           const __half* __restrict__ A,
                                           const __half* __restrict__ W,
                                           int m0, int n0, int k0, int tid)
{
#pragma unroll
    for (int rep = 0; rep < 8; rep++) {
        const int t = tid + rep * 128;        // 0..1023
        const int row = t >> 3;
        const int seg = (t & 7) * 8;          // halves (16B)
        cpa16(&As[row * PAD + seg], &A[(size_t)(m0 + row) * DM + k0 + seg]);
        cpa16(&Bs[row * PAD + seg], &W[(size_t)(n0 + row) * DM + k0 + seg]);
    }
}

__device__ __forceinline__ void gemm128_tc(const __half* __restrict__ A,
                                           const __half* __restrict__ W,
                                           const float* __restrict__ bias,
                                           void* __restrict__ Cout,
                                           int mode)
{
    extern __shared__ __half smg[];
    __half* As = smg;                 // [2][128][PAD]
    __half* Bs = smg + 2 * GSTG;      // [2][128][PAD]

    const int tid  = threadIdx.x;
    const int warp = tid >> 5, lane = tid & 31;
    const int wm = warp >> 1, wn = warp & 1;
    const int lg = lane >> 2, lt = lane & 3;
    const int m0 = blockIdx.y * 128;
    const int n0 = blockIdx.x * 128;

    float acc[4][8][4];
#pragma unroll
    for (int i = 0; i < 4; i++)
#pragma unroll
        for (int j = 0; j < 8; j++)
#pragma unroll
            for (int e = 0; e < 4; e++) acc[i][j][e] = 0.f;

    gemm_stage(As, Bs, A, W, m0, n0, 0, tid);
    CPC();

    for (int k0 = 0; k0 < DM; k0 += KT) {
        const int cur = (k0 >> 6) & 1;
        __syncthreads();
        if (k0 + KT < DM)
            gemm_stage(As + (cur ^ 1) * GSTG, Bs + (cur ^ 1) * GSTG,
                       A, W, m0, n0, k0 + KT, tid);
        CPC();
        CPW1();
        __syncthreads();

        const __half* Ab = As + cur * GSTG;
        const __half* Bb = Bs + cur * GSTG;
#pragma unroll
        for (int ks = 0; ks < 4; ks++) {      // 4 x k16 per 64-half chunk
            unsigned a[4][4], b[8][2];
            const int c = ks * 16 + lt * 2;
#pragma unroll
            for (int mt = 0; mt < 4; mt++) {
                const int r = wm * 64 + mt * 16 + lg;
                a[mt][0] = ldh2(&Ab[r * PAD + c]);
                a[mt][1] = ldh2(&Ab[(r + 8) * PAD + c]);
                a[mt][2] = ldh2(&Ab[r * PAD + c + 8]);
                a[mt][3] = ldh2(&Ab[(r + 8) * PAD + c + 8]);
            }
#pragma unroll
            for (int nt = 0; nt < 8; nt++) {
                const int n = wn * 64 + nt * 8 + lg;
                b[nt][0] = ldh2(&Bb[n * PAD + c]);
                b[nt][1] = ldh2(&Bb[n * PAD + c + 8]);
            }
#pragma unroll
            for (int mt = 0; mt < 4; mt++)
#pragma unroll
                for (int nt = 0; nt < 8; nt++)
                    mma_f16(acc[mt][nt], a[mt], b[nt]);
        }
    }

    // epilogue
    if (mode == 1) {
        float* C = (float*)Cout;
#pragma unroll
        for (int mt = 0; mt < 4; mt++) {
            const int r0 = m0 + wm * 64 + mt * 16 + lg;
#pragma unroll
            for (int nt = 0; nt < 8; nt++) {
                const int col = n0 + wn * 64 + nt * 8 + 2 * lt;
                const float b0 = bias[col], b1 = bias[col + 1];
                *(float2*)&C[(size_t)r0 * DM + col] =
                    make_float2(acc[mt][nt][0] + b0, acc[mt][nt][1] + b1);
                *(float2*)&C[(size_t)(r0 + 8) * DM + col] =
                    make_float2(acc[mt][nt][2] + b0, acc[mt][nt][3] + b1);
            }
        }
    } else if (mode == 0) {
        __half* C = (__half*)Cout;
#pragma unroll
        for (int mt = 0; mt < 4; mt++) {
            const int r0 = m0 + wm * 64 + mt * 16 + lg;
#pragma unroll
            for (int nt = 0; nt < 8; nt++) {
                const int col = n0 + wn * 64 + nt * 8 + 2 * lt;
                *(__half2*)&C[(size_t)r0 * DM + col] =
                    __floats2half2_rn(acc[mt][nt][0], acc[mt][nt][1]);
                *(__half2*)&C[(size_t)(r0 + 8) * DM + col] =
                    __floats2half2_rn(acc[mt][nt][2], acc[mt][nt][3]);
            }
        }
    } else {
        // V: write transposed per-head [b,h,d,s]
        __half* C = (__half*)Cout;
#pragma unroll
        for (int mt = 0; mt < 4; mt++) {
            const int t0 = m0 + wm * 64 + mt * 16 + lg;
#pragma unroll
            for (int nt = 0; nt < 8; nt++) {
                const int col = n0 + wn * 64 + nt * 8 + 2 * lt;
                const int h = col >> 6, d = col & 63;
#pragma unroll
                for (int e = 0; e < 4; e++) {
                    const int t = t0 + (e >> 1) * 8;
                    const int dd = d + (e & 1);
                    const int b = t >> 11, s = t & 2047;
                    C[((size_t)(b * NH + h) * HD + dd) * SQ + s] =
                        __float2half(acc[mt][nt][e]);
                }
            }
        }
    }
}

__global__ __launch_bounds__(128, 2) void qkv_gemm_kernel()
{
    const __half* W; __half* C; int mode;
    if (blockIdx.z == 0)      { W = g_Wt;                   C = g_Q;  mode = 0; }
    else if (blockIdx.z == 1) { W = g_Wt + (size_t)DM*DM;   C = g_K;  mode = 0; }
    else                      { W = g_Wt + (size_t)2*DM*DM; C = g_Vt; mode = 2; }
    gemm128_tc(g_X, W, nullptr, C, mode);
}

__global__ __launch_bounds__(128, 2) void o_gemm_kernel(
    const float* __restrict__ bo, float* __restrict__ out)
{
    gemm128_tc(g_C, g_Wt + (size_t)3*DM*DM, bo, out, 1);
}

// ---------------------------------------------------------------------------
// Flash attention, FP16 TC (m16n8k16), cp.async double-buffered K/V^T tiles.
// 128 queries per CTA, 4 warps x 32 query rows. log2-domain softmax.
// ---------------------------------------------------------------------------
#define APAD 80
#define ATILE (64 * APAD)                       // halves per K/V stage
#define KS_OFF 0
#define VT_OFF (2 * ATILE)                      // 10240
#define PS_OFF (4 * ATILE)                      // 20480
#define ATTN_HALVES (PS_OFF + 128 * APAD)       // 30720
#define BS_BYTE_OFF (ATTN_HALVES * 2)           // 61440
#define ATTN_SMEM_BYTES (BS_BYTE_OFF + 2176 * 4)

__global__ __launch_bounds__(128, 2) void attn_kernel(const float* __restrict__ bt)
{
    extern __shared__ __half sm[];
    __half* Ks = sm + KS_OFF;     // [2][64][APAD] (key, d)
    __half* Vt = sm + VT_OFF;     // [2][64][APAD] (d, key)
    __half* Ps = sm + PS_OFF;     // [128][APAD]  P / Q staging
    float* bsA = (float*)((char*)sm + BS_BYTE_OFF);   // [2175] log2-domain bias

    const int tid  = threadIdx.x;
    const int warp = tid >> 5, lane = tid & 31;
    const int lg = lane >> 2, lt = lane & 3;
    const int bh = blockIdx.y;
    const int b = bh >> 4, h = bh & 15;
    const int q0 = blockIdx.x * 128;

    const __half* gK = g_K  + (size_t)b * SQ * DM + h * HD;
    const __half* gV = g_Vt + (size_t)(b * NH + h) * HD * SQ;

    for (int j = tid; j < 2175; j += 128)
        bsA[j] = bt[(size_t)(q0 + j) * NH + h] * LOG2E;

    // stage Q row tid (64 halves = 16 uint2)
    {
        const __half* src = g_Q + (size_t)(b * SQ + q0 + tid) * DM + h * HD;
#pragma unroll
        for (int rep = 0; rep < 16; rep++)
            *(uint2*)&Ps[tid * APAD + rep * 4] = *(const uint2*)&src[rep * 4];
    }
    __syncwarp();

    // persistent Q fragments: 2 m-tiles x 4 k16-steps
    unsigned qf[2][4][4];
#pragma unroll
    for (int mt = 0; mt < 2; mt++) {
        const int r = warp * 32 + mt * 16 + lg;
#pragma unroll
        for (int ks = 0; ks < 4; ks++) {
            const int c = ks * 16 + lt * 2;
            qf[mt][ks][0] = ldh2(&Ps[r * APAD + c]);
            qf[mt][ks][1] = ldh2(&Ps[(r + 8) * APAD + c]);
            qf[mt][ks][2] = ldh2(&Ps[r * APAD + c + 8]);
            qf[mt][ks][3] = ldh2(&Ps[(r + 8) * APAD + c + 8]);
        }
    }
    __syncwarp();

    // prefetch tile 0 (64 rows x 4 segs of 16B per matrix)
    {
#pragma unroll
        for (int rep = 0; rep < 4; rep++) {
            const int t = tid + rep * 128;    // 0..511
            const int r = t >> 3;
            const int c = (t & 7) * 8;
            if ((t & 512) == 0) {}            // (keep simple: both matrices below)
            cpa16(&Ks[r * APAD + c], &gK[(size_t)r * DM + c]);
            cpa16(&Vt[r * APAD + c], &gV[(size_t)r * SQ + c]);
        }
        CPC();
    }

    float mA[2] = {-1e30f, -1e30f}, mB[2] = {-1e30f, -1e30f};
    float lA[2] = {0.f, 0.f},       lB[2] = {0.f, 0.f};
    float o[2][8][4];
#pragma unroll
    for (int mt = 0; mt < 2; mt++)
#pragma unroll
        for (int nt = 0; nt < 8; nt++)
#pragma unroll
            for (int e = 0; e < 4; e++) o[mt][nt][e] = 0.f;

    for (int k0 = 0, t = 0; k0 < SQ; k0 += 64, t++) {
        const int cur = t & 1;
        __syncthreads();
        if (k0 + 64 < SQ) {
            __half* Kn = Ks + (cur ^ 1) * ATILE;
            __half* Vn = Vt + (cur ^ 1) * ATILE;
#pragma unroll
            for (int rep = 0; rep < 4; rep++) {
                const int tt = tid + rep * 128;
                const int r = tt >> 3;
                const int c = (tt & 7) * 8;
                cpa16(&Kn[r * APAD + c], &gK[(size_t)(k0 + 64 + r) * DM + c]);
                cpa16(&Vn[r * APAD + c], &gV[(size_t)r * SQ + k0 + 64 + c]);
            }
        }
        CPC();
        CPW1();
        __syncthreads();

        const __half* Kb = Ks + cur * ATILE;
        const __half* Vb = Vt + cur * ATILE;

        // ---- S = Q' @ K^T (log2 domain)
        float s[2][8][4];
#pragma unroll
        for (int mt = 0; mt < 2; mt++)
#pragma unroll
            for (int nt = 0; nt < 8; nt++)
#pragma unroll
                for (int e = 0; e < 4; e++) s[mt][nt][e] = 0.f;
#pragma unroll
        for (int ks = 0; ks < 4; ks++) {
            const int c = ks * 16 + lt * 2;
#pragma unroll
            for (int nt = 0; nt < 8; nt++) {
                unsigned bf[2];
                const int n = nt * 8 + lg;
                bf[0] = ldh2(&Kb[n * APAD + c]);
                bf[1] = ldh2(&Kb[n * APAD + c + 8]);
                mma_f16(s[0][nt], qf[0][ks], bf);
                mma_f16(s[1][nt], qf[1][ks], bf);
            }
        }

        // ---- bias + online softmax
#pragma unroll
        for (int mt = 0; mt < 2; mt++) {
            const int rA = warp * 32 + mt * 16 + lg;
            const int rB = rA + 8;
            const int jbA = rA + 2047 - k0;
            const int jbB = rB + 2047 - k0;
            float mxA = -1e30f, mxB = -1e30f;
#pragma unroll
            for (int nt = 0; nt < 8; nt++) {
                const int col = nt * 8 + 2 * lt;
                s[mt][nt][0] += bsA[jbA - col];
                s[mt][nt][1] += bsA[jbA - col - 1];
                s[mt][nt][2] += bsA[jbB - col];
                s[mt][nt][3] += bsA[jbB - col - 1];
                mxA = fmaxf(mxA, fmaxf(s[mt][nt][0], s[mt][nt][1]));
                mxB = fmaxf(mxB, fmaxf(s[mt][nt][2], s[mt][nt][3]));
            }
#pragma unroll
            for (int off = 1; off <= 2; off <<= 1) {
                mxA = fmaxf(mxA, __shfl_xor_sync(0xffffffffu, mxA, off));
                mxB = fmaxf(mxB, __shfl_xor_sync(0xffffffffu, mxB, off));
            }
            const float mnA = fmaxf(mA[mt], mxA);
            const float mnB = fmaxf(mB[mt], mxB);
            const float crA = ex2(mA[mt] - mnA);
            const float crB = ex2(mB[mt] - mnB);
            float sA = 0.f, sB = 0.f;
#pragma unroll
            for (int nt = 0; nt < 8; nt++) {
                s[mt][nt][0] = ex2(s[mt][nt][0] - mnA);
                s[mt][nt][1] = ex2(s[mt][nt][1] - mnA);
                s[mt][nt][2] = ex2(s[mt][nt][2] - mnB);
                s[mt][nt][3] = ex2(s[mt][nt][3] - mnB);
                sA += s[mt][nt][0] + s[mt][nt][1];
                sB += s[mt][nt][2] + s[mt][nt][3];
                const int col = nt * 8 + 2 * lt;
                *(__half2*)&Ps[rA * APAD + col] =
                    __floats2half2_rn(s[mt][nt][0], s[mt][nt][1]);
                *(__half2*)&Ps[rB * APAD + col] =
                    __floats2half2_rn(s[mt][nt][2], s[mt][nt][3]);
            }
#pragma unroll
            for (int off = 1; off <= 2; off <<= 1) {
                sA += __shfl_xor_sync(0xffffffffu, sA, off);
                sB += __shfl_xor_sync(0xffffffffu, sB, off);
            }
            lA[mt] = lA[mt] * crA + sA;
            lB[mt] = lB[mt] * crB + sB;
            mA[mt] = mnA; mB[mt] = mnB;
#pragma unroll
            for (int nt = 0; nt < 8; nt++) {
                o[mt][nt][0] *= crA; o[mt][nt][1] *= crA;
                o[mt][nt][2] *= crB; o[mt][nt][3] *= crB;
            }
        }
        __syncwarp();

        // ---- acc += P @ V (K-dim = 64 keys -> 4 k16 steps)
#pragma unroll
        for (int ks = 0; ks < 4; ks++) {
            const int c = ks * 16 + lt * 2;
            unsigned pa[2][4];
#pragma unroll
            for (int mt = 0; mt < 2; mt++) {
                const int rA = warp * 32 + mt * 16 + lg;
                pa[mt][0] = ldh2(&Ps[rA * APAD + c]);
                pa[mt][1] = ldh2(&Ps[(rA + 8) * APAD + c]);
                pa[mt][2] = ldh2(&Ps[rA * APAD + c + 8]);
                pa[mt][3] = ldh2(&Ps[(rA + 8) * APAD + c + 8]);
            }
#pragma unroll
            for (int nt = 0; nt < 8; nt++) {
                unsigned bf[2];
                const int n = nt * 8 + lg;
                bf[0] = ldh2(&Vb[n * APAD + c]);
                bf[1] = ldh2(&Vb[n * APAD + c + 8]);
                mma_f16(o[0][nt], pa[0], bf);
                mma_f16(o[1][nt], pa[1], bf);
            }
        }
    }

    // ---- normalize + write ctx [B,S,D] fp16
#pragma unroll
    for (int mt = 0; mt < 2; mt++) {
        const int rA = warp * 32 + mt * 16 + lg;
        const float invA = 1.f / lA[mt];
        const float invB = 1.f / lB[mt];
        __half* dstA = g_C + (size_t)(b * SQ + q0 + rA) * DM + h * HD;
        __half* dstB = g_C + (size_t)(b * SQ + q0 + rA + 8) * DM + h * HD;
#pragma unroll
        for (int nt = 0; nt < 8; nt++) {
            const int col = nt * 8 + 2 * lt;
            *(__half2*)&dstA[col] =
                __floats2half2_rn(o[mt][nt][0] * invA, o[mt][nt][1] * invA);
            *(__half2*)&dstB[col] =
                __floats2half2_rn(o[mt][nt][2] * invB, o[mt][nt][3] * invB);
        }
    }
}

// ---------------------------------------------------------------------------
extern "C" void kernel_launch(void* const* d_in, const int* in_sizes, int n_in,
                              void* d_out, int out_size)
{
    (void)in_sizes; (void)n_in; (void)out_size;
    const float* x   = (const float*)d_in[0];
    const float* Wq  = (const float*)d_in[1];
    const float* Wk  = (const float*)d_in[2];
    const float* Wv  = (const float*)d_in[3];
    const float* Wo  = (const float*)d_in[4];
    const float* bo  = (const float*)d_in[5];
    const float* bt  = (const float*)d_in[6];
    float* out = (float*)d_out;

    // 0) fp16 prepass
    dim3 g0((MT * DM / 4 + 255) / 256, 5);
    prep_kernel<<<g0, 256>>>(x, Wq, Wk, Wv, Wo);

    // 1) QKV projections
    cudaFuncSetAttribute(qkv_gemm_kernel,
                         cudaFuncAttributeMaxDynamicSharedMemorySize,
                         GEMM_SMEM_BYTES);
    dim3 g1(DM / 128, MT / 128, 3);
    qkv_gemm_kernel<<<g1, 128, GEMM_SMEM_BYTES>>>();

    // 2) attention
    cudaFuncSetAttribute(attn_kernel,
                         cudaFuncAttributeMaxDynamicSharedMemorySize,
                         ATTN_SMEM_BYTES);
    dim3 g2(SQ / 128, BB * NH);
    attn_kernel<<<g2, 128, ATTN_SMEM_BYTES>>>(bt);

    // 3) output projection + bias
    cudaFuncSetAttribute(o_gemm_kernel,
                         cudaFuncAttributeMaxDynamicSharedMemorySize,
                         GEMM_SMEM_BYTES);
    dim3 g3(DM / 128, MT / 128);
    o_gemm_kernel<<<g3, 128, GEMM_SMEM_BYTES>>>(bo, out);
}